// round 3
// baseline (speedup 1.0000x reference)
#include <cuda_runtime.h>
#include <math.h>

#define B_    8
#define N_    8192
#define C_    91
#define CM_   90
#define K_    1000
#define T_    128
#define MAXT_ 100
#define NPROB (B_*CM_)

#define BBOX_CLIP 4.135166556742356f
#define IOU_THR   0.3f

// ---------------- scratch ----------------
__device__ float g_scores[B_*CM_*N_];
__device__ float g_nboxes[NPROB*K_*4];
__device__ float g_kept[NPROB*K_];
__device__ int   g_cnt[NPROB];
__device__ unsigned int g_selT[NPROB];   // class selection threshold (bits)
__device__ unsigned int g_excl[NPROB];   // best excluded candidate (bits), 0 if none
__device__ unsigned int g_Lbits[B_];
__device__ int   g_need[NPROB];

// ---------------- K1: softmax + transpose ----------------
__global__ void __launch_bounds__(256) softmax_kernel(const float* __restrict__ cls)
{
    __shared__ float tile[C_][33];
    int cta  = blockIdx.x;
    int b    = cta / (N_/32);
    int n0   = (cta % (N_/32)) * 32;
    int warp = threadIdx.x >> 5;
    int lane = threadIdx.x & 31;

    for (int rr = 0; rr < 4; rr++) {
        int r = warp*4 + rr;
        const float* row = cls + ((size_t)b*N_ + n0 + r) * C_;
        float v0 = row[lane];
        float v1 = row[lane + 32];
        bool  h2 = (lane + 64) < C_;
        float v2 = h2 ? row[lane + 64] : -3.0e38f;
        float m = fmaxf(fmaxf(v0, v1), v2);
        #pragma unroll
        for (int off = 16; off; off >>= 1)
            m = fmaxf(m, __shfl_xor_sync(0xFFFFFFFFu, m, off));
        float e0 = expf(v0 - m);
        float e1 = expf(v1 - m);
        float e2 = h2 ? expf(v2 - m) : 0.f;
        float s = e0 + e1 + e2;
        #pragma unroll
        for (int off = 16; off; off >>= 1)
            s += __shfl_xor_sync(0xFFFFFFFFu, s, off);
        tile[lane][r]      = e0 / s;
        tile[lane + 32][r] = e1 / s;
        if (h2) tile[lane + 64][r] = e2 / s;
    }
    __syncthreads();
    for (int k = threadIdx.x; k < CM_*32; k += 256) {
        int c = k >> 5;
        int r = k & 31;
        g_scores[((size_t)b*CM_ + c)*N_ + n0 + r] = tile[c+1][r];
    }
}

// ---------------- fast suffix-select (blockDim 256, nb >= 256, 2 barriers) --------
__device__ void sel2(const unsigned int* hist, int nb, unsigned int target,
                     int* s_bin, int* s_above)
{
    __shared__ unsigned int wtot[8];
    int t = threadIdx.x, lane = t & 31, wid = t >> 5;
    int chunk = nb >> 8;
    unsigned int csum = 0;
    for (int k = 0; k < chunk; k++) csum += hist[t*chunk + k];
    unsigned int v = csum;
    #pragma unroll
    for (int off = 1; off < 32; off <<= 1) {
        unsigned int u = __shfl_down_sync(0xFFFFFFFFu, v, off);
        if (lane + off < 32) v += u;
    }
    if (lane == 0) wtot[wid] = v;
    if (t == 0) *s_bin = -1;
    __syncthreads();
    unsigned int after = 0;
    for (int wd = wid + 1; wd < 8; wd++) after += wtot[wd];
    unsigned int above = after + (v - csum);   // strictly after chunk t
    if (above < target && above + csum >= target) {
        unsigned int run = above;
        for (int i = chunk - 1; i >= 0; i--) {
            unsigned int h = hist[t*chunk + i];
            if (run < target && run + h >= target) {
                *s_bin = t*chunk + i;
                *s_above = (int)run;
            }
            run += h;
        }
    }
    __syncthreads();
}

// descending bitonic sort of n u64 keys in smem (n power of 2)
__device__ void bitonic_desc(unsigned long long* a, int n)
{
    for (unsigned int k = 2; k <= (unsigned)n; k <<= 1) {
        for (unsigned int j = k >> 1; j > 0; j >>= 1) {
            for (unsigned int i = threadIdx.x; i < (unsigned)n; i += blockDim.x) {
                unsigned int ixj = i ^ j;
                if (ixj > i) {
                    unsigned long long x = a[i], y = a[ixj];
                    bool desc = ((i & k) == 0);
                    if (desc ? (x < y) : (x > y)) { a[i] = y; a[ixj] = x; }
                }
            }
            __syncthreads();
        }
    }
}

// ---------------- box decode ----------------
__device__ __forceinline__ void decode_one(
    const float* __restrict__ box_outputs, const float* __restrict__ anchors,
    int b, int cm, int idx, float h, float w,
    float& b0, float& b1, float& b2, float& b3)
{
    const float* anc = anchors + ((size_t)b*N_ + idx)*4;
    float a0 = anc[0], a1 = anc[1], a2 = anc[2], a3 = anc[3];
    const float* e4 = box_outputs + ((size_t)b*N_ + idx)*(C_*4) + (cm+1)*4;
    float ty = e4[0] / 10.f;
    float tx = e4[1] / 10.f;
    float th = fminf(e4[2] / 5.f, BBOX_CLIP);
    float tw = fminf(e4[3] / 5.f, BBOX_CLIP);
    float ah = a2 - a0, aw = a3 - a1;
    float acy = a0 + 0.5f*ah, acx = a1 + 0.5f*aw;
    float cy = ty*ah + acy, cx = tx*aw + acx;
    float hh = expf(th)*ah, ww = expf(tw)*aw;
    b0 = cy - 0.5f*hh; b1 = cx - 0.5f*ww;
    b2 = cy + 0.5f*hh; b3 = cx + 0.5f*ww;
    b0 = fminf(fmaxf(b0, 0.f), h); b0 /= h;
    b1 = fminf(fmaxf(b1, 0.f), w); b1 /= w;
    b2 = fminf(fmaxf(b2, 0.f), h); b2 /= h;
    b3 = fminf(fmaxf(b3, 0.f), w); b3 /= w;
}

// ---------------- K2: top-128 select + decode + bitmask NMS ----------------
__global__ void __launch_bounds__(256) topk_nms_kernel(
    const float* __restrict__ box_outputs,
    const float* __restrict__ anchors,
    const float* __restrict__ image_info)
{
    __shared__ unsigned int hist[8192];
    __shared__ unsigned long long cand[256];
    __shared__ float y0[T_], x0[T_], y1[T_], x1[T_], ar[T_];
    __shared__ uint4 msk[T_];
    __shared__ unsigned char passf[T_], keptf[T_];
    __shared__ int s_bin, s_above, s_cnt;

    int blk = blockIdx.x;
    int t = threadIdx.x;
    const float* sc = g_scores + (size_t)blk * N_;

    // L1: 13-bit key histogram
    for (int i = t; i < 8192; i += 256) hist[i] = 0;
    __syncthreads();
    for (int i = t; i < N_; i += 256) {
        unsigned int bits = __float_as_uint(sc[i]);
        atomicAdd(&hist[bits >> 18], 1u);
    }
    __syncthreads();
    sel2(hist, 8192, T_, &s_bin, &s_above);
    int B1 = s_bin, A1 = s_above;

    // L2: next 11 bits within bin B1
    for (int i = t; i < 2048; i += 256) hist[i] = 0;
    __syncthreads();
    for (int i = t; i < N_; i += 256) {
        unsigned int bits = __float_as_uint(sc[i]);
        if ((int)(bits >> 18) == B1) atomicAdd(&hist[(bits >> 7) & 0x7FF], 1u);
    }
    __syncthreads();
    sel2(hist, 2048, (unsigned)(T_ - A1), &s_bin, &s_above);
    int B2 = s_bin, A2 = s_above;
    unsigned int T = ((unsigned)B1 << 18) | ((unsigned)B2 << 7);

    // compact (cap 256)
    if (t == 0) s_cnt = 0;
    __syncthreads();
    for (int i = t; i < N_; i += 256) {
        unsigned int bits = __float_as_uint(sc[i]);
        if (bits >= T) {
            int p = atomicAdd(&s_cnt, 1);
            if (p < 256)
                cand[p] = ((unsigned long long)bits << 32) |
                          (unsigned long long)(0xFFFFFFFFu - (unsigned)i);
        }
    }
    __syncthreads();

    if (s_cnt > 256) {
        // L3 fallback: last 7 bits (256-bin padded)
        if (t < 256) hist[t] = 0;
        __syncthreads();
        unsigned int hi24 = ((unsigned)B1 << 11) | (unsigned)B2;
        for (int i = t; i < N_; i += 256) {
            unsigned int bits = __float_as_uint(sc[i]);
            if ((bits >> 7) == hi24) atomicAdd(&hist[bits & 0x7F], 1u);
        }
        __syncthreads();
        sel2(hist, 256, (unsigned)(T_ - A1 - A2), &s_bin, &s_above);
        T = ((unsigned)B1 << 18) | ((unsigned)B2 << 7) | (unsigned)s_bin;
        if (t == 0) s_cnt = 0;
        __syncthreads();
        for (int i = t; i < N_; i += 256) {
            unsigned int bits = __float_as_uint(sc[i]);
            if (bits >= T) {
                int p = atomicAdd(&s_cnt, 1);
                if (p < 256)
                    cand[p] = ((unsigned long long)bits << 32) |
                              (unsigned long long)(0xFFFFFFFFu - (unsigned)i);
            }
        }
        __syncthreads();
        if (s_cnt > 256) {     // pathological duplicates: defer to fixup
            if (t == 0) {
                g_cnt[blk] = 0;
                g_selT[blk] = 0xFFFFFFFFu;
                g_excl[blk] = 0xFFFFFFFFu;
            }
            return;
        }
    }

    int Csel = s_cnt;
    if (t >= Csel && t < 256) cand[t] = 0ull;
    __syncthreads();

    bitonic_desc(cand, 256);

    int nv = Csel < T_ ? Csel : T_;
    int b  = blk / CM_;
    int cm = blk % CM_;
    float h = image_info[b*4 + 0];
    float w = image_info[b*4 + 1];

    if (t < nv) {
        unsigned long long key = cand[t];
        float s = __uint_as_float((unsigned int)(key >> 32));
        int idx = (int)(0xFFFFFFFFu - (unsigned int)key);
        float b0, b1, b2, b3;
        decode_one(box_outputs, anchors, b, cm, idx, h, w, b0, b1, b2, b3);
        y0[t] = b0; x0[t] = b1; y1[t] = b2; x1[t] = b3;
        ar[t] = fmaxf(b2 - b0, 0.f) * fmaxf(b3 - b1, 0.f);
        passf[t] = (s > 0.f) ? 1 : 0;
        float* nb = g_nboxes + ((size_t)blk*K_ + t)*4;
        nb[0] = b0; nb[1] = b1; nb[2] = b2; nb[3] = b3;
    }
    __syncthreads();

    // parallel IoU bitmask: msk[t] bit j set iff IoU(j,t) > thr for j < t
    if (t < nv) {
        unsigned int m0 = 0, m1 = 0, m2 = 0, m3 = 0;
        float ty0 = y0[t], tx0 = x0[t], ty1 = y1[t], tx1 = x1[t], ta = ar[t];
        for (int j = 0; j < t; j++) {
            float ih = fmaxf(fminf(y1[j], ty1) - fmaxf(y0[j], ty0), 0.f);
            float iw = fmaxf(fminf(x1[j], tx1) - fmaxf(x0[j], tx0), 0.f);
            float inter = ih * iw;
            float iou = inter / (((ar[j] + ta) - inter) + 1e-8f);
            if (iou > IOU_THR) {
                if (j < 32)       m0 |= 1u << j;
                else if (j < 64)  m1 |= 1u << (j - 32);
                else if (j < 96)  m2 |= 1u << (j - 64);
                else              m3 |= 1u << (j - 96);
            }
        }
        msk[t] = make_uint4(m0, m1, m2, m3);
    }
    __syncthreads();

    // serial greedy resolution (single thread, register bitmaps)
    if (t == 0) {
        unsigned int k0 = 0, k1 = 0, k2 = 0, k3 = 0;
        for (int i = 0; i < nv; i++) {
            uint4 m = msk[i];
            bool sup = ((m.x & k0) | (m.y & k1) | (m.z & k2) | (m.w & k3)) != 0u;
            bool kp = passf[i] && !sup;
            keptf[i] = kp;
            if (kp) {
                if (i < 32)       k0 |= 1u << i;
                else if (i < 64)  k1 |= 1u << (i - 32);
                else if (i < 96)  k2 |= 1u << (i - 64);
                else              k3 |= 1u << (i - 96);
            }
        }
    }
    __syncthreads();

    if (t < nv) {
        float s = __uint_as_float((unsigned int)(cand[t] >> 32));
        g_kept[(size_t)blk*K_ + t] = keptf[t] ? s : -1.0f;
    }
    if (t == 0) {
        g_cnt[blk]  = nv;
        g_selT[blk] = T;
        g_excl[blk] = (Csel > nv) ? (unsigned int)(cand[nv] >> 32) : 0u;
    }
}

// ---------------- K3: per-image L (lower bound on 100th kept) + fixup gate --------
__global__ void __launch_bounds__(256) computeL_kernel()
{
    __shared__ unsigned int hist[8192];
    __shared__ int cnts[CM_];
    __shared__ int s_bin, s_above;

    int b = blockIdx.x;
    int t = threadIdx.x;
    const float* ks = g_kept + (size_t)b * CM_ * K_;

    if (t < CM_) cnts[t] = g_cnt[b*CM_ + t];
    for (int i = t; i < 8192; i += 256) hist[i] = 0;
    __syncthreads();

    for (int k = t; k < CM_*T_; k += 256) {
        int c = k >> 7, i = k & (T_-1);
        if (i < cnts[c]) {
            float v = ks[(size_t)c*K_ + i];
            if (v > 0.f) atomicAdd(&hist[__float_as_uint(v) >> 18], 1u);
        }
    }
    __syncthreads();
    sel2(hist, 8192, MAXT_, &s_bin, &s_above);
    int B1 = s_bin, A1 = s_above;

    unsigned int L;
    if (B1 < 0) {
        L = 1u;                     // fewer than 100 kept: every positive score qualifies
    } else {
        for (int i = t; i < 2048; i += 256) hist[i] = 0;
        __syncthreads();
        for (int k = t; k < CM_*T_; k += 256) {
            int c = k >> 7, i = k & (T_-1);
            if (i < cnts[c]) {
                float v = ks[(size_t)c*K_ + i];
                if (v > 0.f) {
                    unsigned int bits = __float_as_uint(v);
                    if ((int)(bits >> 18) == B1) atomicAdd(&hist[(bits >> 7) & 0x7FF], 1u);
                }
            }
        }
        __syncthreads();
        sel2(hist, 2048, (unsigned)(MAXT_ - A1), &s_bin, &s_above);
        L = ((unsigned)B1 << 18) | ((unsigned)s_bin << 7);   // bin floor: valid lower bound
    }
    if (t == 0) g_Lbits[b] = L;

    if (t < CM_) {
        int c = t;
        int need = (g_selT[b*CM_ + c] > L) || (g_excl[b*CM_ + c] >= L);
        g_need[b*CM_ + c] = need;
    }
}

// ---------------- K4: fixup (rare; full NMS where prefix was insufficient) --------
__global__ void __launch_bounds__(256) fixup_kernel(
    const float* __restrict__ box_outputs,
    const float* __restrict__ anchors,
    const float* __restrict__ image_info)
{
    __shared__ unsigned long long cand[2048];
    __shared__ unsigned int scanbuf[256];
    __shared__ float y0[K_], x0[K_], y1[K_], x1[K_], ar[K_];
    __shared__ unsigned char sup[K_];
    __shared__ int s_bin, s_above, s_cnt;
    unsigned int* hist = (unsigned int*)cand;

    int blk = blockIdx.x;
    if (!g_need[blk]) return;

    int t = threadIdx.x;
    int b = blk / CM_;
    int cm = blk % CM_;
    unsigned int L = g_Lbits[b];
    const float* sc = g_scores + (size_t)blk * N_;

    // count scores with bits >= L
    int cnt = 0;
    for (int i = t; i < N_; i += 256)
        cnt += (__float_as_uint(sc[i]) >= L) ? 1 : 0;
    scanbuf[t] = (unsigned)cnt;
    __syncthreads();
    for (int off = 128; off > 0; off >>= 1) {
        if (t < off) scanbuf[t] += scanbuf[t + off];
        __syncthreads();
    }
    int count = (int)scanbuf[0];
    __syncthreads();

    if (count <= g_cnt[blk]) return;

    unsigned int T;
    if (count <= K_) {
        T = L;
    } else {
        // exact top-1000 threshold (13-bit / 11-bit / 7-bit padded)
        for (int i = t; i < 8192; i += 256)
            if (i < 8192) ((unsigned int*)cand)[0] = ((unsigned int*)cand)[0]; // no-op guard
        for (int i = t; i < 4096; i += 256) hist[i] = 0;
        __syncthreads();
        // level 1 over 13-bit key folded into 4096 bins? use two sub-passes:
        // simpler: 12-bit key (bits >> 19) then 12-bit (bits >> 7 & 0xFFF)
        for (int i = t; i < N_; i += 256)
            atomicAdd(&hist[__float_as_uint(sc[i]) >> 19], 1u);
        __syncthreads();
        sel2(hist, 4096, K_, &s_bin, &s_above);
        int B1 = s_bin, A1 = s_above;

        for (int i = t; i < 4096; i += 256) hist[i] = 0;
        __syncthreads();
        for (int i = t; i < N_; i += 256) {
            unsigned int bits = __float_as_uint(sc[i]);
            if ((int)(bits >> 19) == B1) atomicAdd(&hist[(bits >> 7) & 0xFFF], 1u);
        }
        __syncthreads();
        sel2(hist, 4096, (unsigned)(K_ - A1), &s_bin, &s_above);
        int B2 = s_bin, A2 = s_above;

        if (t < 256) hist[t] = 0;
        __syncthreads();
        unsigned int hi = ((unsigned)B1 << 12) | (unsigned)B2;
        for (int i = t; i < N_; i += 256) {
            unsigned int bits = __float_as_uint(sc[i]);
            if ((bits >> 7) == hi) atomicAdd(&hist[bits & 0x7F], 1u);
        }
        __syncthreads();
        sel2(hist, 256, (unsigned)(K_ - A1 - A2), &s_bin, &s_above);
        T = ((unsigned)B1 << 19) | ((unsigned)B2 << 7) | (unsigned)s_bin;
        __syncthreads();
    }

    if (t == 0) s_cnt = 0;
    __syncthreads();
    for (int i = t; i < N_; i += 256) {
        unsigned int bits = __float_as_uint(sc[i]);
        if (bits >= T) {
            int p = atomicAdd(&s_cnt, 1);
            if (p < 2048)
                cand[p] = ((unsigned long long)bits << 32) |
                          (unsigned long long)(0xFFFFFFFFu - (unsigned)i);
        }
    }
    __syncthreads();
    int Csel = s_cnt < 2048 ? s_cnt : 2048;
    for (int i = t; i < 2048; i += 256)
        if (i >= Csel) cand[i] = 0ull;
    __syncthreads();

    bitonic_desc(cand, 2048);

    int M = count < K_ ? count : K_;
    if (M > Csel) M = Csel;
    float h = image_info[b*4 + 0];
    float w = image_info[b*4 + 1];

    for (int i = t; i < M; i += 256) {
        unsigned long long key = cand[i];
        float s = __uint_as_float((unsigned int)(key >> 32));
        int idx = (int)(0xFFFFFFFFu - (unsigned int)key);
        float b0, b1, b2, b3;
        decode_one(box_outputs, anchors, b, cm, idx, h, w, b0, b1, b2, b3);
        y0[i] = b0; x0[i] = b1; y1[i] = b2; x1[i] = b3;
        ar[i] = fmaxf(b2 - b0, 0.f) * fmaxf(b3 - b1, 0.f);
        sup[i] = (s > 0.f) ? 0 : 1;
        float* nb = g_nboxes + ((size_t)blk*K_ + i)*4;
        nb[0] = b0; nb[1] = b1; nb[2] = b2; nb[3] = b3;
    }
    __syncthreads();

    for (int i = 0; i < M; i++) {
        if (!sup[i]) {
            float iy0 = y0[i], ix0 = x0[i], iy1 = y1[i], ix1 = x1[i], ia = ar[i];
            for (int j = i + 1 + t; j < M; j += 256) {
                if (sup[j]) continue;
                float ih = fmaxf(fminf(iy1, y1[j]) - fmaxf(iy0, y0[j]), 0.f);
                float iw = fmaxf(fminf(ix1, x1[j]) - fmaxf(ix0, x0[j]), 0.f);
                float inter = ih * iw;
                float iou = inter / (((ia + ar[j]) - inter) + 1e-8f);
                if (iou > IOU_THR) sup[j] = 1;
            }
        }
        __syncthreads();
    }

    for (int i = t; i < M; i += 256) {
        float s = __uint_as_float((unsigned int)(cand[i] >> 32));
        g_kept[(size_t)blk*K_ + i] = (!sup[i]) ? s : -1.0f;
    }
    if (t == 0) g_cnt[blk] = M;
}

// ---------------- K5: per-image global top-100 + output ----------------
__global__ void __launch_bounds__(256) final_kernel(
    const float* __restrict__ image_info, float* __restrict__ out)
{
    __shared__ unsigned int hist[8192];
    __shared__ unsigned long long cand[256];
    __shared__ int cnts[CM_];
    __shared__ int s_bin, s_above, s_cnt, s_valid;

    int b = blockIdx.x;
    int t = threadIdx.x;
    const float* ks = g_kept + (size_t)b * CM_ * K_;
    unsigned int L = g_Lbits[b];

    if (t < CM_) cnts[t] = g_cnt[b*CM_ + t];
    if (t == 0) { s_cnt = 0; s_valid = 0; }
    __syncthreads();

    // one-pass collect of kept scores >= L
    for (int c = 0; c < CM_; c++) {
        int cn = cnts[c];
        for (int i = t; i < cn; i += 256) {
            float v = ks[(size_t)c*K_ + i];
            unsigned int bits = __float_as_uint(v);
            if (v > 0.f && bits >= L) {
                int p = atomicAdd(&s_cnt, 1);
                if (p < 256) {
                    unsigned int flat = (unsigned)(c*K_ + i);
                    cand[p] = ((unsigned long long)bits << 32) |
                              (unsigned long long)(0xFFFFFFFFu - flat);
                }
            }
        }
    }
    __syncthreads();

    if (s_cnt > 256) {
        // fallback: exact top-100 threshold over kept prefixes, then recompact
        for (int i = t; i < 8192; i += 256) hist[i] = 0;
        __syncthreads();
        for (int c = 0; c < CM_; c++) {
            int cn = cnts[c];
            for (int i = t; i < cn; i += 256) {
                float v = ks[(size_t)c*K_ + i];
                if (v > 0.f) atomicAdd(&hist[__float_as_uint(v) >> 18], 1u);
            }
        }
        __syncthreads();
        sel2(hist, 8192, MAXT_, &s_bin, &s_above);
        int B1 = s_bin, A1 = s_above;

        for (int i = t; i < 2048; i += 256) hist[i] = 0;
        __syncthreads();
        for (int c = 0; c < CM_; c++) {
            int cn = cnts[c];
            for (int i = t; i < cn; i += 256) {
                float v = ks[(size_t)c*K_ + i];
                if (v > 0.f) {
                    unsigned int bits = __float_as_uint(v);
                    if ((int)(bits >> 18) == B1) atomicAdd(&hist[(bits >> 7) & 0x7FF], 1u);
                }
            }
        }
        __syncthreads();
        sel2(hist, 2048, (unsigned)(MAXT_ - A1), &s_bin, &s_above);
        int B2 = s_bin, A2 = s_above;

        if (t < 256) hist[t] = 0;
        __syncthreads();
        unsigned int hi = ((unsigned)B1 << 11) | (unsigned)B2;
        for (int c = 0; c < CM_; c++) {
            int cn = cnts[c];
            for (int i = t; i < cn; i += 256) {
                float v = ks[(size_t)c*K_ + i];
                if (v > 0.f) {
                    unsigned int bits = __float_as_uint(v);
                    if ((bits >> 7) == hi) atomicAdd(&hist[bits & 0x7F], 1u);
                }
            }
        }
        __syncthreads();
        sel2(hist, 256, (unsigned)(MAXT_ - A1 - A2), &s_bin, &s_above);
        unsigned int T100 = ((unsigned)B1 << 18) | ((unsigned)B2 << 7) | (unsigned)s_bin;

        if (t == 0) s_cnt = 0;
        __syncthreads();
        for (int c = 0; c < CM_; c++) {
            int cn = cnts[c];
            for (int i = t; i < cn; i += 256) {
                float v = ks[(size_t)c*K_ + i];
                unsigned int bits = __float_as_uint(v);
                if (v > 0.f && bits >= T100) {
                    int p = atomicAdd(&s_cnt, 1);
                    if (p < 256) {
                        unsigned int flat = (unsigned)(c*K_ + i);
                        cand[p] = ((unsigned long long)bits << 32) |
                                  (unsigned long long)(0xFFFFFFFFu - flat);
                    }
                }
            }
        }
        __syncthreads();
    }

    int Csel = s_cnt < 256 ? s_cnt : 256;
    if (t >= Csel && t < 256) cand[t] = 0ull;
    __syncthreads();

    bitonic_desc(cand, 256);

    float h = image_info[b*4 + 0];
    float w = image_info[b*4 + 1];
    for (int i = t; i < MAXT_; i += 256) {
        unsigned long long key = cand[i];
        float s = __uint_as_float((unsigned int)(key >> 32));
        bool valid = (s > 0.f);
        float b0 = 0.f, b1 = 0.f, b2 = 0.f, b3 = 0.f, cl = 0.f, so = 0.f;
        if (valid) {
            unsigned int flat = 0xFFFFFFFFu - (unsigned int)key;
            int c = flat / K_;
            int k = flat % K_;
            const float* nb = g_nboxes + ((size_t)(b*CM_ + c)*K_ + k)*4;
            b0 = nb[0]*h; b1 = nb[1]*w; b2 = nb[2]*h; b3 = nb[3]*w;
            cl = (float)(c + 1);
            so = s;
            atomicAdd(&s_valid, 1);
        }
        float* ob = out + B_ + (size_t)(b*MAXT_ + i)*4;
        ob[0] = b0; ob[1] = b1; ob[2] = b2; ob[3] = b3;
        out[B_ + B_*MAXT_*4 + b*MAXT_ + i] = cl;
        out[B_ + B_*MAXT_*4 + B_*MAXT_ + b*MAXT_ + i] = so;
    }
    __syncthreads();
    if (t == 0) out[b] = (float)s_valid;
}

// ---------------- launch ----------------
extern "C" void kernel_launch(void* const* d_in, const int* in_sizes, int n_in,
                              void* d_out, int out_size)
{
    const float* cls  = (const float*)d_in[0];
    const float* box  = (const float*)d_in[1];
    const float* anc  = (const float*)d_in[2];
    const float* info = (const float*)d_in[3];
    float* out = (float*)d_out;

    softmax_kernel<<<B_*(N_/32), 256>>>(cls);
    topk_nms_kernel<<<NPROB, 256>>>(box, anc, info);
    computeL_kernel<<<B_, 256>>>();
    fixup_kernel<<<NPROB, 256>>>(box, anc, info);
    final_kernel<<<B_, 256>>>(info, out);
}

// round 4
// speedup vs baseline: 1.6956x; 1.6956x over previous
#include <cuda_runtime.h>
#include <math.h>

#define B_    8
#define N_    8192
#define C_    91
#define CM_   90
#define K_    1000
#define T_    128
#define MAXT_ 100
#define NPROB (B_*CM_)

#define BBOX_CLIP 4.135166556742356f
#define IOU_THR   0.3f

// padded histogram indexing: conflict-free chunk reads + spread atomics
#define HPAD(i) ((i) + ((i) >> 5))
#define HSZ(n)  ((n) + ((n) >> 5))

// ---------------- scratch ----------------
__device__ float g_scores[B_*CM_*N_];
__device__ float g_nboxes[NPROB*K_*4];
__device__ float g_kept[NPROB*K_];
__device__ int   g_cnt[NPROB];
__device__ unsigned int g_selT[NPROB];
__device__ unsigned int g_excl[NPROB];
__device__ unsigned int g_Lbits[B_];
__device__ int   g_need[NPROB];

// ---------------- K1: softmax + transpose ----------------
__global__ void __launch_bounds__(256) softmax_kernel(const float* __restrict__ cls)
{
    __shared__ float tile[C_][33];
    int cta  = blockIdx.x;
    int b    = cta / (N_/32);
    int n0   = (cta % (N_/32)) * 32;
    int warp = threadIdx.x >> 5;
    int lane = threadIdx.x & 31;

    for (int rr = 0; rr < 4; rr++) {
        int r = warp*4 + rr;
        const float* row = cls + ((size_t)b*N_ + n0 + r) * C_;
        float v0 = row[lane];
        float v1 = row[lane + 32];
        bool  h2 = (lane + 64) < C_;
        float v2 = h2 ? row[lane + 64] : -3.0e38f;
        float m = fmaxf(fmaxf(v0, v1), v2);
        #pragma unroll
        for (int off = 16; off; off >>= 1)
            m = fmaxf(m, __shfl_xor_sync(0xFFFFFFFFu, m, off));
        float e0 = expf(v0 - m);
        float e1 = expf(v1 - m);
        float e2 = h2 ? expf(v2 - m) : 0.f;
        float s = e0 + e1 + e2;
        #pragma unroll
        for (int off = 16; off; off >>= 1)
            s += __shfl_xor_sync(0xFFFFFFFFu, s, off);
        tile[lane][r]      = e0 / s;
        tile[lane + 32][r] = e1 / s;
        if (h2) tile[lane + 64][r] = e2 / s;
    }
    __syncthreads();
    for (int k = threadIdx.x; k < CM_*32; k += 256) {
        int c = k >> 5;
        int r = k & 31;
        g_scores[((size_t)b*CM_ + c)*N_ + n0 + r] = tile[c+1][r];
    }
}

// ---------------- suffix-select over padded histogram (2 barriers) ----------------
// hist is HPAD-indexed. Finds bin with above < target <= above + hist[bin].
__device__ void sel2(const unsigned int* hist, int nb, unsigned int target,
                     int* s_bin, int* s_above)
{
    __shared__ unsigned int wtot[8];
    int t = threadIdx.x, lane = t & 31, wid = t >> 5;
    int chunk = nb >> 8;
    unsigned int csum = 0;
    for (int k = 0; k < chunk; k++) csum += hist[HPAD(t*chunk + k)];
    unsigned int v = csum;
    #pragma unroll
    for (int off = 1; off < 32; off <<= 1) {
        unsigned int u = __shfl_down_sync(0xFFFFFFFFu, v, off);
        if (lane + off < 32) v += u;
    }
    if (lane == 0) wtot[wid] = v;
    if (t == 0) *s_bin = -1;
    __syncthreads();
    unsigned int after = 0;
    for (int wd = wid + 1; wd < 8; wd++) after += wtot[wd];
    unsigned int above = after + (v - csum);
    if (above < target && above + csum >= target) {
        unsigned int run = above;
        for (int i = chunk - 1; i >= 0; i--) {
            unsigned int h = hist[HPAD(t*chunk + i)];
            if (run < target && run + h >= target) {
                *s_bin = t*chunk + i;
                *s_above = (int)run;
            }
            run += h;
        }
    }
    __syncthreads();
}

// descending bitonic sort of n u64 keys in smem
__device__ void bitonic_desc(unsigned long long* a, int n)
{
    for (unsigned int k = 2; k <= (unsigned)n; k <<= 1) {
        for (unsigned int j = k >> 1; j > 0; j >>= 1) {
            for (unsigned int i = threadIdx.x; i < (unsigned)n; i += blockDim.x) {
                unsigned int ixj = i ^ j;
                if (ixj > i) {
                    unsigned long long x = a[i], y = a[ixj];
                    bool desc = ((i & k) == 0);
                    if (desc ? (x < y) : (x > y)) { a[i] = y; a[ixj] = x; }
                }
            }
            __syncthreads();
        }
    }
}

// ---------------- box decode ----------------
__device__ __forceinline__ void decode_one(
    const float* __restrict__ box_outputs, const float* __restrict__ anchors,
    int b, int cm, int idx, float h, float w,
    float& b0, float& b1, float& b2, float& b3)
{
    const float* anc = anchors + ((size_t)b*N_ + idx)*4;
    float a0 = anc[0], a1 = anc[1], a2 = anc[2], a3 = anc[3];
    const float* e4 = box_outputs + ((size_t)b*N_ + idx)*(C_*4) + (cm+1)*4;
    float ty = e4[0] / 10.f;
    float tx = e4[1] / 10.f;
    float th = fminf(e4[2] / 5.f, BBOX_CLIP);
    float tw = fminf(e4[3] / 5.f, BBOX_CLIP);
    float ah = a2 - a0, aw = a3 - a1;
    float acy = a0 + 0.5f*ah, acx = a1 + 0.5f*aw;
    float cy = ty*ah + acy, cx = tx*aw + acx;
    float hh = expf(th)*ah, ww = expf(tw)*aw;
    b0 = cy - 0.5f*hh; b1 = cx - 0.5f*ww;
    b2 = cy + 0.5f*hh; b3 = cx + 0.5f*ww;
    b0 = fminf(fmaxf(b0, 0.f), h); b0 /= h;
    b1 = fminf(fmaxf(b1, 0.f), w); b1 /= w;
    b2 = fminf(fmaxf(b2, 0.f), h); b2 /= h;
    b3 = fminf(fmaxf(b3, 0.f), w); b3 /= w;
}

// ---------------- K2: top-128 select + decode + bitmask NMS ----------------
__global__ void __launch_bounds__(256) topk_nms_kernel(
    const float* __restrict__ box_outputs,
    const float* __restrict__ anchors,
    const float* __restrict__ image_info)
{
    __shared__ unsigned int hist[HSZ(2048)];
    __shared__ unsigned long long cand[256];
    __shared__ float y0[T_], x0[T_], y1[T_], x1[T_], ar[T_];
    __shared__ uint4 msk[T_];
    __shared__ unsigned char passf[T_], keptf[T_];
    __shared__ int s_bin, s_above, s_cnt;

    int blk = blockIdx.x;
    int t = threadIdx.x;
    const float* sc = g_scores + (size_t)blk * N_;

    // L1: top 11 bits (2048 bins)
    for (int i = t; i < HSZ(2048); i += 256) hist[i] = 0;
    __syncthreads();
    for (int i = t; i < N_; i += 256) {
        unsigned int bits = __float_as_uint(sc[i]);
        atomicAdd(&hist[HPAD(bits >> 21)], 1u);
    }
    __syncthreads();
    sel2(hist, 2048, T_, &s_bin, &s_above);
    int B1 = s_bin, A1 = s_above;

    // L2: next 11 bits within bin B1
    for (int i = t; i < HSZ(2048); i += 256) hist[i] = 0;
    __syncthreads();
    for (int i = t; i < N_; i += 256) {
        unsigned int bits = __float_as_uint(sc[i]);
        if ((int)(bits >> 21) == B1) atomicAdd(&hist[HPAD((bits >> 10) & 0x7FF)], 1u);
    }
    __syncthreads();
    sel2(hist, 2048, (unsigned)(T_ - A1), &s_bin, &s_above);
    int B2 = s_bin, A2 = s_above;
    unsigned int T = ((unsigned)B1 << 21) | ((unsigned)B2 << 10);

    // compact (cap 256)
    if (t == 0) s_cnt = 0;
    __syncthreads();
    for (int i = t; i < N_; i += 256) {
        unsigned int bits = __float_as_uint(sc[i]);
        if (bits >= T) {
            int p = atomicAdd(&s_cnt, 1);
            if (p < 256)
                cand[p] = ((unsigned long long)bits << 32) |
                          (unsigned long long)(0xFFFFFFFFu - (unsigned)i);
        }
    }
    __syncthreads();

    if (s_cnt > 256) {
        // L3 fallback: last 10 bits (1024 bins)
        for (int i = t; i < HSZ(1024); i += 256) hist[i] = 0;
        __syncthreads();
        unsigned int hi22 = ((unsigned)B1 << 11) | (unsigned)B2;
        for (int i = t; i < N_; i += 256) {
            unsigned int bits = __float_as_uint(sc[i]);
            if ((bits >> 10) == hi22) atomicAdd(&hist[HPAD(bits & 0x3FF)], 1u);
        }
        __syncthreads();
        sel2(hist, 1024, (unsigned)(T_ - A1 - A2), &s_bin, &s_above);
        T = ((unsigned)B1 << 21) | ((unsigned)B2 << 10) | (unsigned)s_bin;
        if (t == 0) s_cnt = 0;
        __syncthreads();
        for (int i = t; i < N_; i += 256) {
            unsigned int bits = __float_as_uint(sc[i]);
            if (bits >= T) {
                int p = atomicAdd(&s_cnt, 1);
                if (p < 256)
                    cand[p] = ((unsigned long long)bits << 32) |
                              (unsigned long long)(0xFFFFFFFFu - (unsigned)i);
            }
        }
        __syncthreads();
        if (s_cnt > 256) {        // pathological exact-duplicate flood: defer
            if (t == 0) {
                g_cnt[blk] = 0;
                g_selT[blk] = 0xFFFFFFFFu;
                g_excl[blk] = 0xFFFFFFFFu;
            }
            return;
        }
    }

    int Csel = s_cnt;
    if (t >= Csel && t < 256) cand[t] = 0ull;
    __syncthreads();

    bitonic_desc(cand, 256);

    int nv = Csel < T_ ? Csel : T_;
    int b  = blk / CM_;
    int cm = blk % CM_;
    float h = image_info[b*4 + 0];
    float w = image_info[b*4 + 1];

    if (t < nv) {
        unsigned long long key = cand[t];
        float s = __uint_as_float((unsigned int)(key >> 32));
        int idx = (int)(0xFFFFFFFFu - (unsigned int)key);
        float b0, b1, b2, b3;
        decode_one(box_outputs, anchors, b, cm, idx, h, w, b0, b1, b2, b3);
        y0[t] = b0; x0[t] = b1; y1[t] = b2; x1[t] = b3;
        ar[t] = fmaxf(b2 - b0, 0.f) * fmaxf(b3 - b1, 0.f);
        passf[t] = (s > 0.f) ? 1 : 0;
        float* nb = g_nboxes + ((size_t)blk*K_ + t)*4;
        nb[0] = b0; nb[1] = b1; nb[2] = b2; nb[3] = b3;
    }
    __syncthreads();

    // parallel IoU bitmask: msk[t] bit j set iff IoU(j,t) > thr for j < t
    if (t < nv) {
        unsigned int m0 = 0, m1 = 0, m2 = 0, m3 = 0;
        float ty0 = y0[t], tx0 = x0[t], ty1 = y1[t], tx1 = x1[t], ta = ar[t];
        for (int j = 0; j < t; j++) {
            float ih = fmaxf(fminf(y1[j], ty1) - fmaxf(y0[j], ty0), 0.f);
            float iw = fmaxf(fminf(x1[j], tx1) - fmaxf(x0[j], tx0), 0.f);
            float inter = ih * iw;
            float iou = inter / (((ar[j] + ta) - inter) + 1e-8f);
            if (iou > IOU_THR) {
                if (j < 32)       m0 |= 1u << j;
                else if (j < 64)  m1 |= 1u << (j - 32);
                else if (j < 96)  m2 |= 1u << (j - 64);
                else              m3 |= 1u << (j - 96);
            }
        }
        msk[t] = make_uint4(m0, m1, m2, m3);
    }
    __syncthreads();

    if (t == 0) {
        unsigned int k0 = 0, k1 = 0, k2 = 0, k3 = 0;
        for (int i = 0; i < nv; i++) {
            uint4 m = msk[i];
            bool sup = ((m.x & k0) | (m.y & k1) | (m.z & k2) | (m.w & k3)) != 0u;
            bool kp = passf[i] && !sup;
            keptf[i] = kp;
            if (kp) {
                if (i < 32)       k0 |= 1u << i;
                else if (i < 64)  k1 |= 1u << (i - 32);
                else if (i < 96)  k2 |= 1u << (i - 64);
                else              k3 |= 1u << (i - 96);
            }
        }
    }
    __syncthreads();

    if (t < nv) {
        float s = __uint_as_float((unsigned int)(cand[t] >> 32));
        g_kept[(size_t)blk*K_ + t] = keptf[t] ? s : -1.0f;
    }
    if (t == 0) {
        g_cnt[blk]  = nv;
        g_selT[blk] = T;
        g_excl[blk] = (Csel > nv) ? (unsigned int)(cand[nv] >> 32) : 0u;
    }
}

// ---------------- K3: per-image L + fixup gate ----------------
__global__ void __launch_bounds__(256) computeL_kernel()
{
    __shared__ unsigned int hist[HSZ(2048)];
    __shared__ int cnts[CM_];
    __shared__ int s_bin, s_above;

    int b = blockIdx.x;
    int t = threadIdx.x;
    const float* ks = g_kept + (size_t)b * CM_ * K_;

    if (t < CM_) cnts[t] = g_cnt[b*CM_ + t];
    for (int i = t; i < HSZ(2048); i += 256) hist[i] = 0;
    __syncthreads();

    for (int k = t; k < CM_*T_; k += 256) {
        int c = k >> 7, i = k & (T_-1);
        if (i < cnts[c]) {
            float v = ks[(size_t)c*K_ + i];
            if (v > 0.f) atomicAdd(&hist[HPAD(__float_as_uint(v) >> 21)], 1u);
        }
    }
    __syncthreads();
    sel2(hist, 2048, MAXT_, &s_bin, &s_above);
    int B1 = s_bin, A1 = s_above;

    unsigned int L;
    if (B1 < 0) {
        L = 1u;
    } else {
        for (int i = t; i < HSZ(2048); i += 256) hist[i] = 0;
        __syncthreads();
        for (int k = t; k < CM_*T_; k += 256) {
            int c = k >> 7, i = k & (T_-1);
            if (i < cnts[c]) {
                float v = ks[(size_t)c*K_ + i];
                if (v > 0.f) {
                    unsigned int bits = __float_as_uint(v);
                    if ((int)(bits >> 21) == B1) atomicAdd(&hist[HPAD((bits >> 10) & 0x7FF)], 1u);
                }
            }
        }
        __syncthreads();
        sel2(hist, 2048, (unsigned)(MAXT_ - A1), &s_bin, &s_above);
        L = ((unsigned)B1 << 21) | ((unsigned)s_bin << 10);   // bin floor: valid lower bound
    }
    if (t == 0) g_Lbits[b] = L;

    if (t < CM_) {
        int c = t;
        int need = (g_selT[b*CM_ + c] > L) || (g_excl[b*CM_ + c] >= L);
        g_need[b*CM_ + c] = need;
    }
}

// ---------------- K4: fixup (rare full-NMS path) ----------------
__global__ void __launch_bounds__(256) fixup_kernel(
    const float* __restrict__ box_outputs,
    const float* __restrict__ anchors,
    const float* __restrict__ image_info)
{
    __shared__ unsigned long long cand[2048];
    __shared__ unsigned int scanbuf[256];
    __shared__ float y0[K_], x0[K_], y1[K_], x1[K_], ar[K_];
    __shared__ unsigned char sup[K_];
    __shared__ int s_bin, s_above, s_cnt;
    unsigned int* hist = (unsigned int*)cand;   // used strictly before cand

    int blk = blockIdx.x;
    if (!g_need[blk]) return;

    int t = threadIdx.x;
    int b = blk / CM_;
    int cm = blk % CM_;
    unsigned int L = g_Lbits[b];
    const float* sc = g_scores + (size_t)blk * N_;

    int cnt = 0;
    for (int i = t; i < N_; i += 256)
        cnt += (__float_as_uint(sc[i]) >= L) ? 1 : 0;
    scanbuf[t] = (unsigned)cnt;
    __syncthreads();
    for (int off = 128; off > 0; off >>= 1) {
        if (t < off) scanbuf[t] += scanbuf[t + off];
        __syncthreads();
    }
    int count = (int)scanbuf[0];
    __syncthreads();

    if (count <= g_cnt[blk]) return;

    unsigned int T;
    if (count <= K_) {
        T = L;
    } else {
        for (int i = t; i < HSZ(2048); i += 256) hist[i] = 0;
        __syncthreads();
        for (int i = t; i < N_; i += 256)
            atomicAdd(&hist[HPAD(__float_as_uint(sc[i]) >> 21)], 1u);
        __syncthreads();
        sel2(hist, 2048, K_, &s_bin, &s_above);
        int B1 = s_bin, A1 = s_above;

        for (int i = t; i < HSZ(2048); i += 256) hist[i] = 0;
        __syncthreads();
        for (int i = t; i < N_; i += 256) {
            unsigned int bits = __float_as_uint(sc[i]);
            if ((int)(bits >> 21) == B1) atomicAdd(&hist[HPAD((bits >> 10) & 0x7FF)], 1u);
        }
        __syncthreads();
        sel2(hist, 2048, (unsigned)(K_ - A1), &s_bin, &s_above);
        int B2 = s_bin, A2 = s_above;

        for (int i = t; i < HSZ(1024); i += 256) hist[i] = 0;
        __syncthreads();
        unsigned int hi22 = ((unsigned)B1 << 11) | (unsigned)B2;
        for (int i = t; i < N_; i += 256) {
            unsigned int bits = __float_as_uint(sc[i]);
            if ((bits >> 10) == hi22) atomicAdd(&hist[HPAD(bits & 0x3FF)], 1u);
        }
        __syncthreads();
        sel2(hist, 1024, (unsigned)(K_ - A1 - A2), &s_bin, &s_above);
        T = ((unsigned)B1 << 21) | ((unsigned)B2 << 10) | (unsigned)s_bin;
        __syncthreads();
    }

    if (t == 0) s_cnt = 0;
    __syncthreads();
    for (int i = t; i < N_; i += 256) {
        unsigned int bits = __float_as_uint(sc[i]);
        if (bits >= T) {
            int p = atomicAdd(&s_cnt, 1);
            if (p < 2048)
                cand[p] = ((unsigned long long)bits << 32) |
                          (unsigned long long)(0xFFFFFFFFu - (unsigned)i);
        }
    }
    __syncthreads();
    int Csel = s_cnt < 2048 ? s_cnt : 2048;
    for (int i = t; i < 2048; i += 256)
        if (i >= Csel) cand[i] = 0ull;
    __syncthreads();

    bitonic_desc(cand, 2048);

    int M = count < K_ ? count : K_;
    if (M > Csel) M = Csel;
    float h = image_info[b*4 + 0];
    float w = image_info[b*4 + 1];

    for (int i = t; i < M; i += 256) {
        unsigned long long key = cand[i];
        float s = __uint_as_float((unsigned int)(key >> 32));
        int idx = (int)(0xFFFFFFFFu - (unsigned int)key);
        float b0, b1, b2, b3;
        decode_one(box_outputs, anchors, b, cm, idx, h, w, b0, b1, b2, b3);
        y0[i] = b0; x0[i] = b1; y1[i] = b2; x1[i] = b3;
        ar[i] = fmaxf(b2 - b0, 0.f) * fmaxf(b3 - b1, 0.f);
        sup[i] = (s > 0.f) ? 0 : 1;
        float* nb = g_nboxes + ((size_t)blk*K_ + i)*4;
        nb[0] = b0; nb[1] = b1; nb[2] = b2; nb[3] = b3;
    }
    __syncthreads();

    for (int i = 0; i < M; i++) {
        if (!sup[i]) {
            float iy0 = y0[i], ix0 = x0[i], iy1 = y1[i], ix1 = x1[i], ia = ar[i];
            for (int j = i + 1 + t; j < M; j += 256) {
                if (sup[j]) continue;
                float ih = fmaxf(fminf(iy1, y1[j]) - fmaxf(iy0, y0[j]), 0.f);
                float iw = fmaxf(fminf(ix1, x1[j]) - fmaxf(ix0, x0[j]), 0.f);
                float inter = ih * iw;
                float iou = inter / (((ia + ar[j]) - inter) + 1e-8f);
                if (iou > IOU_THR) sup[j] = 1;
            }
        }
        __syncthreads();
    }

    for (int i = t; i < M; i += 256) {
        float s = __uint_as_float((unsigned int)(cand[i] >> 32));
        g_kept[(size_t)blk*K_ + i] = (!sup[i]) ? s : -1.0f;
    }
    if (t == 0) g_cnt[blk] = M;
}

// ---------------- K5: per-image global top-100 + output ----------------
__global__ void __launch_bounds__(256) final_kernel(
    const float* __restrict__ image_info, float* __restrict__ out)
{
    __shared__ unsigned int hist[HSZ(2048)];
    __shared__ unsigned long long cand[256];
    __shared__ int cnts[CM_];
    __shared__ int s_bin, s_above, s_cnt, s_valid;

    int b = blockIdx.x;
    int t = threadIdx.x;
    const float* ks = g_kept + (size_t)b * CM_ * K_;
    unsigned int L = g_Lbits[b];

    if (t < CM_) cnts[t] = g_cnt[b*CM_ + t];
    if (t == 0) { s_cnt = 0; s_valid = 0; }
    __syncthreads();

    // one-pass collect of kept scores >= L
    for (int c = 0; c < CM_; c++) {
        int cn = cnts[c];
        for (int i = t; i < cn; i += 256) {
            float v = ks[(size_t)c*K_ + i];
            unsigned int bits = __float_as_uint(v);
            if (v > 0.f && bits >= L) {
                int p = atomicAdd(&s_cnt, 1);
                if (p < 256) {
                    unsigned int flat = (unsigned)(c*K_ + i);
                    cand[p] = ((unsigned long long)bits << 32) |
                              (unsigned long long)(0xFFFFFFFFu - flat);
                }
            }
        }
    }
    __syncthreads();

    if (s_cnt > 256) {
        // exact top-100 threshold over kept prefixes, recompact
        for (int i = t; i < HSZ(2048); i += 256) hist[i] = 0;
        __syncthreads();
        for (int c = 0; c < CM_; c++) {
            int cn = cnts[c];
            for (int i = t; i < cn; i += 256) {
                float v = ks[(size_t)c*K_ + i];
                if (v > 0.f) atomicAdd(&hist[HPAD(__float_as_uint(v) >> 21)], 1u);
            }
        }
        __syncthreads();
        sel2(hist, 2048, MAXT_, &s_bin, &s_above);
        int B1 = s_bin, A1 = s_above;

        for (int i = t; i < HSZ(2048); i += 256) hist[i] = 0;
        __syncthreads();
        for (int c = 0; c < CM_; c++) {
            int cn = cnts[c];
            for (int i = t; i < cn; i += 256) {
                float v = ks[(size_t)c*K_ + i];
                if (v > 0.f) {
                    unsigned int bits = __float_as_uint(v);
                    if ((int)(bits >> 21) == B1) atomicAdd(&hist[HPAD((bits >> 10) & 0x7FF)], 1u);
                }
            }
        }
        __syncthreads();
        sel2(hist, 2048, (unsigned)(MAXT_ - A1), &s_bin, &s_above);
        int B2 = s_bin, A2 = s_above;

        for (int i = t; i < HSZ(1024); i += 256) hist[i] = 0;
        __syncthreads();
        unsigned int hi22 = ((unsigned)B1 << 11) | (unsigned)B2;
        for (int c = 0; c < CM_; c++) {
            int cn = cnts[c];
            for (int i = t; i < cn; i += 256) {
                float v = ks[(size_t)c*K_ + i];
                if (v > 0.f) {
                    unsigned int bits = __float_as_uint(v);
                    if ((bits >> 10) == hi22) atomicAdd(&hist[HPAD(bits & 0x3FF)], 1u);
                }
            }
        }
        __syncthreads();
        sel2(hist, 1024, (unsigned)(MAXT_ - A1 - A2), &s_bin, &s_above);
        unsigned int T100 = ((unsigned)B1 << 21) | ((unsigned)B2 << 10) | (unsigned)s_bin;

        if (t == 0) s_cnt = 0;
        __syncthreads();
        for (int c = 0; c < CM_; c++) {
            int cn = cnts[c];
            for (int i = t; i < cn; i += 256) {
                float v = ks[(size_t)c*K_ + i];
                unsigned int bits = __float_as_uint(v);
                if (v > 0.f && bits >= T100) {
                    int p = atomicAdd(&s_cnt, 1);
                    if (p < 256) {
                        unsigned int flat = (unsigned)(c*K_ + i);
                        cand[p] = ((unsigned long long)bits << 32) |
                                  (unsigned long long)(0xFFFFFFFFu - flat);
                    }
                }
            }
        }
        __syncthreads();
    }

    int Csel = s_cnt < 256 ? s_cnt : 256;
    if (t >= Csel && t < 256) cand[t] = 0ull;
    __syncthreads();

    bitonic_desc(cand, 256);

    float h = image_info[b*4 + 0];
    float w = image_info[b*4 + 1];
    for (int i = t; i < MAXT_; i += 256) {
        unsigned long long key = cand[i];
        float s = __uint_as_float((unsigned int)(key >> 32));
        bool valid = (s > 0.f);
        float b0 = 0.f, b1 = 0.f, b2 = 0.f, b3 = 0.f, cl = 0.f, so = 0.f;
        if (valid) {
            unsigned int flat = 0xFFFFFFFFu - (unsigned int)key;
            int c = flat / K_;
            int k = flat % K_;
            const float* nb = g_nboxes + ((size_t)(b*CM_ + c)*K_ + k)*4;
            b0 = nb[0]*h; b1 = nb[1]*w; b2 = nb[2]*h; b3 = nb[3]*w;
            cl = (float)(c + 1);
            so = s;
            atomicAdd(&s_valid, 1);
        }
        float* ob = out + B_ + (size_t)(b*MAXT_ + i)*4;
        ob[0] = b0; ob[1] = b1; ob[2] = b2; ob[3] = b3;
        out[B_ + B_*MAXT_*4 + b*MAXT_ + i] = cl;
        out[B_ + B_*MAXT_*4 + B_*MAXT_ + b*MAXT_ + i] = so;
    }
    __syncthreads();
    if (t == 0) out[b] = (float)s_valid;
}

// ---------------- launch ----------------
extern "C" void kernel_launch(void* const* d_in, const int* in_sizes, int n_in,
                              void* d_out, int out_size)
{
    const float* cls  = (const float*)d_in[0];
    const float* box  = (const float*)d_in[1];
    const float* anc  = (const float*)d_in[2];
    const float* info = (const float*)d_in[3];
    float* out = (float*)d_out;

    softmax_kernel<<<B_*(N_/32), 256>>>(cls);
    topk_nms_kernel<<<NPROB, 256>>>(box, anc, info);
    computeL_kernel<<<B_, 256>>>();
    fixup_kernel<<<NPROB, 256>>>(box, anc, info);
    final_kernel<<<B_, 256>>>(info, out);
}